// round 1
// baseline (speedup 1.0000x reference)
#include <cuda_runtime.h>
#include <math.h>

#define NEG_INF (-1e30f)

// Problem constants
#define Bn 8
#define Tn 128
#define Dn 512
#define Hn 512
#define Vn 64
#define Un 32
#define Cn 65   // V + 1

// Scratch (allocation-free rules: __device__ globals)
__device__ float g_proj[Bn * Tn * Hn];                 // 2 MB
__device__ float g_den[Bn * Tn * Cn * Cn];             // [b][t][c][k]; k=0 blank raw, k>=1 exp(lex), ~17.3 MB

// ---------------------------------------------------------------------------
// Kernel 1: proj = frames @ W_frame   (M=1024, N=512, K=512)
// BM=BN=64, BK=16, 256 threads, 4x4 micro-tile
// ---------------------------------------------------------------------------
__global__ __launch_bounds__(256) void k_proj(const float* __restrict__ A,
                                              const float* __restrict__ Bm) {
    __shared__ float As[16][64];
    __shared__ float Bs[16][64];

    const int tx = threadIdx.x & 15;
    const int ty = threadIdx.x >> 4;
    const int tid = threadIdx.x;
    const int bm = blockIdx.y * 64;
    const int bn = blockIdx.x * 64;

    float acc[4][4];
#pragma unroll
    for (int i = 0; i < 4; i++)
#pragma unroll
        for (int j = 0; j < 4; j++) acc[i][j] = 0.f;

    for (int kc = 0; kc < Dn; kc += 16) {
#pragma unroll
        for (int l = 0; l < 4; l++) {
            int e = tid + l * 256;
            int k = e & 15, m = e >> 4;
            As[k][m] = A[(size_t)(bm + m) * Dn + kc + k];
        }
#pragma unroll
        for (int l = 0; l < 4; l++) {
            int e = tid + l * 256;
            int n = e & 63, k = e >> 6;
            Bs[k][n] = Bm[(size_t)(kc + k) * Hn + bn + n];
        }
        __syncthreads();
#pragma unroll
        for (int kk = 0; kk < 16; kk++) {
            float4 av = *reinterpret_cast<const float4*>(&As[kk][ty * 4]);
            float4 bv = *reinterpret_cast<const float4*>(&Bs[kk][tx * 4]);
            float a[4] = {av.x, av.y, av.z, av.w};
            float b[4] = {bv.x, bv.y, bv.z, bv.w};
#pragma unroll
            for (int i = 0; i < 4; i++)
#pragma unroll
                for (int j = 0; j < 4; j++) acc[i][j] += a[i] * b[j];
        }
        __syncthreads();
    }

#pragma unroll
    for (int i = 0; i < 4; i++)
#pragma unroll
        for (int j = 0; j < 4; j++)
            g_proj[(size_t)(bm + ty * 4 + i) * Hn + bn + tx * 4 + j] = acc[i][j];
}

// ---------------------------------------------------------------------------
// Kernel 2: per-(b,t) 65x65 logits tile, fused tanh + epilogue exp
//   logits[c][k] = sum_h tanh(proj[bt][h] + ce[c][h]) * Wout[h][k]
//   store k=0 raw (blank), k>=1 exp() (lex)
// 256 threads (16x16), 5x5 micro-tile over padded 80x80.
// ---------------------------------------------------------------------------
__global__ __launch_bounds__(256) void k_logits(const float* __restrict__ ce,
                                                const float* __restrict__ Wout) {
    const int bt = blockIdx.x;          // 0..1023
    __shared__ float p[Hn];             // proj row
    __shared__ float Jt[80 * 65];       // [c][kk], row stride 65 (kk<64 used)
    __shared__ float Wt[64 * 80];       // [kk][ko], ko padded to 80

    const int tid = threadIdx.x;
    const int tx = tid & 15;
    const int ty = tid >> 4;

    for (int i = tid; i < Hn; i += 256) p[i] = g_proj[(size_t)bt * Hn + i];
    // zero padding rows c = 65..79 of Jt (written once, never overwritten)
    for (int i = tid; i < 15 * 65; i += 256) Jt[65 * 65 + i] = 0.f;
    __syncthreads();

    float acc[5][5];
#pragma unroll
    for (int i = 0; i < 5; i++)
#pragma unroll
        for (int j = 0; j < 5; j++) acc[i][j] = 0.f;

    for (int kc = 0; kc < Hn; kc += 64) {
        // fill Jt: 65 x 64 tanh values
        for (int e = tid; e < 65 * 64; e += 256) {
            int c = e >> 6, kk = e & 63;
            Jt[c * 65 + kk] = tanhf(p[kc + kk] + ce[(size_t)c * Hn + kc + kk]);
        }
        // fill Wt: 64 x 80 (pad ko>=65 with 0)
        for (int e = tid; e < 64 * 80; e += 256) {
            int kk = e / 80, ko = e % 80;
            Wt[e] = (ko < Cn) ? Wout[(size_t)(kc + kk) * Cn + ko] : 0.f;
        }
        __syncthreads();
#pragma unroll 8
        for (int kk = 0; kk < 64; kk++) {
            float a[5], b[5];
#pragma unroll
            for (int i = 0; i < 5; i++) a[i] = Jt[(ty + 16 * i) * 65 + kk];
#pragma unroll
            for (int j = 0; j < 5; j++) b[j] = Wt[kk * 80 + tx + 16 * j];
#pragma unroll
            for (int i = 0; i < 5; i++)
#pragma unroll
                for (int j = 0; j < 5; j++) acc[i][j] += a[i] * b[j];
        }
        __syncthreads();
    }

    float* outp = g_den + (size_t)bt * (Cn * Cn);
#pragma unroll
    for (int i = 0; i < 5; i++) {
        int c = ty + 16 * i;
        if (c >= Cn) continue;
#pragma unroll
        for (int j = 0; j < 5; j++) {
            int k = tx + 16 * j;
            if (k >= Cn) continue;
            float v = acc[i][j];
            outp[c * Cn + k] = (k == 0) ? v : expf(v);
        }
    }
}

// ---------------------------------------------------------------------------
// Kernel 3: the two scans, one block per batch.
// tid 0..63  : denominator state v+1  (matvec over pre-exponentiated lex)
// tid 127    : denominator state 0 (stay only)
// tid 64..96 : numerator states j = tid-64 (0..32)
// Tile (65*65 floats) double-buffered with register prefetch of t+1.
// ---------------------------------------------------------------------------
__device__ __forceinline__ float log_add_exp(float a, float b) {
    float m = fmaxf(a, b);
    float d = fminf(a, b) - m;
    return m + log1pf(expf(d));
}

__global__ __launch_bounds__(128) void k_scan(const int* __restrict__ num_frames,
                                              const int* __restrict__ labels,
                                              const int* __restrict__ num_labels,
                                              float* __restrict__ out) {
    const int b = blockIdx.x;
    const int tid = threadIdx.x;
    const int Tb = num_frames[b];

    __shared__ float alpha[Cn];       // denominator alpha
    __shared__ float anum[Un + 1];    // numerator alpha
    __shared__ float ea[Cn];          // exp(alpha - amax)
    __shared__ int ctx[Un + 1];       // ctx[0]=0, ctx[j]=labels[b][j-1]
    __shared__ float tile[2][Cn * Cn];

    if (tid < Un + 1) {
        ctx[tid] = (tid == 0) ? 0 : labels[b * Un + tid - 1];
        anum[tid] = (tid == 0) ? 0.f : NEG_INF;
    }
    if (tid < Cn) alpha[tid] = (tid == 0) ? 0.f : NEG_INF;

    const float* base = g_den + (size_t)b * Tn * (Cn * Cn);
    // load tile 0
#pragma unroll
    for (int k = 0; k < 34; k++) {
        int i = tid + k * 128;
        if (i < Cn * Cn) tile[0][i] = base[i];
    }
    __syncthreads();

    for (int t = 0; t < Tb; t++) {
        const int cur = t & 1;
        const float* Tt = tile[cur];

        // issue prefetch of tile t+1 into registers (overlaps compute)
        float pre[34];
        const bool do_pre = (t + 1 < Tb);
        const float* bnext = base + (size_t)(t + 1) * (Cn * Cn);
#pragma unroll
        for (int k = 0; k < 34; k++) {
            int i = tid + k * 128;
            if (do_pre && i < Cn * Cn) pre[k] = bnext[i];
        }

        // amax over alpha (redundant per-thread, cheap)
        float m0 = NEG_INF, m1 = NEG_INF;
#pragma unroll 4
        for (int c = 0; c < 64; c += 2) {
            m0 = fmaxf(m0, alpha[c]);
            m1 = fmaxf(m1, alpha[c + 1]);
        }
        float amax = fmaxf(fmaxf(m0, m1), alpha[64]);

        if (tid < Cn) ea[tid] = expf(alpha[tid] - amax);
        __syncthreads();

        float nv = 0.f;      // new denominator value for this thread's state
        float nnum = 0.f;    // new numerator value

        if (tid < 64) {
            const int v = tid;
            float s0 = 0.f, s1 = 0.f, s2 = 0.f, s3 = 0.f;
#pragma unroll 8
            for (int c = 0; c < 64; c += 4) {
                s0 += ea[c]     * Tt[c * Cn + v + 1];
                s1 += ea[c + 1] * Tt[(c + 1) * Cn + v + 1];
                s2 += ea[c + 2] * Tt[(c + 2) * Cn + v + 1];
                s3 += ea[c + 3] * Tt[(c + 3) * Cn + v + 1];
            }
            float s = (s0 + s1) + (s2 + s3) + ea[64] * Tt[64 * Cn + v + 1];
            float mv = amax + logf(s);
            float stay = alpha[v + 1] + Tt[(v + 1) * Cn];   // blank at k=0
            nv = log_add_exp(stay, mv);
        } else if (tid == 127) {
            nv = alpha[0] + Tt[0];                          // new alpha[0] = stay[0]
        } else if (tid < 64 + Un + 1) {
            const int j = tid - 64;
            float a1 = anum[j] + Tt[ctx[j] * Cn];           // blank at context
            float sh = NEG_INF;
            if (j > 0) {
                // lex_num[j-1] = log(E[ctx[j-1]][labels[j-1]]) ; labels[j-1] == ctx[j]
                sh = anum[j - 1] + logf(Tt[ctx[j - 1] * Cn + ctx[j]]);
            }
            nnum = log_add_exp(a1, sh);
        }
        __syncthreads();

        if (tid < 64) alpha[tid + 1] = nv;
        else if (tid == 127) alpha[0] = nv;
        else if (tid < 64 + Un + 1) anum[tid - 64] = nnum;

        // commit prefetch into the other buffer
#pragma unroll
        for (int k = 0; k < 34; k++) {
            int i = tid + k * 128;
            if (do_pre && i < Cn * Cn) tile[1 - cur][i] = pre[k];
        }
        __syncthreads();
    }

    if (tid == 0) {
        float m = NEG_INF;
        for (int c = 0; c < Cn; c++) m = fmaxf(m, alpha[c]);
        float s = 0.f;
        for (int c = 0; c < Cn; c++) s += expf(alpha[c] - m);
        float den = m + logf(s);
        float num = anum[num_labels[b]];
        out[b] = den - num;
    }
}

// ---------------------------------------------------------------------------
extern "C" void kernel_launch(void* const* d_in, const int* in_sizes, int n_in,
                              void* d_out, int out_size) {
    const float* frames = (const float*)d_in[0];   // (8,128,512)
    const float* Wf     = (const float*)d_in[1];   // (512,512)
    const float* ce     = (const float*)d_in[2];   // (65,512)
    const float* Wo     = (const float*)d_in[3];   // (512,65)
    const int* nf       = (const int*)d_in[4];     // (8,)
    const int* labels   = (const int*)d_in[5];     // (8,32)
    const int* nl       = (const int*)d_in[6];     // (8,)
    float* out = (float*)d_out;                    // (8,)

    k_proj<<<dim3(Hn / 64, (Bn * Tn) / 64), 256>>>(frames, Wf);
    k_logits<<<Bn * Tn, 256>>>(ce, Wo);
    k_scan<<<Bn, 128>>>(nf, labels, nl, out);
}